// round 10
// baseline (speedup 1.0000x reference)
#include <cuda_runtime.h>
#include <math.h>

#define BN   8
#define TT   12
#define NN   200
#define CIN  2
#define HH   64
#define DD   32
#define HST  64
#define GW   66      // CIN + HH
#define GIN  198     // GW * 3
#define GROUPS 8
#define GPB    18
#define GRID   (GROUPS*GPB)   // 144 blocks, <=148 SMs, all co-resident
#define NTH    1024
#define MAXR   12

// ---- smem layout (floats) ----
#define OFF_A    0          // A tile: 12*200 = 2400
#define OFF_P    2400       // Pg 12*32, Pm 12*32 = 768
#define OFF_SD   3168       // state_dy 12*32 = 384
#define OFF_U    3552       // u 12*64 = 768
#define OFF_W    4320       // wc1 32 | wm1 32
#define OFF_GRU  4384       // gru scratch 12 warps * 96 = 1152
#define OFF_CP   5536       // split-K partials 25*12*66 = 19800 (also Q stage)
#define OFF_Z    25336      // Z 12*198 = 2376
#define SMEMF    27712      // *4 = 110848 bytes
#define QS_G     OFF_CP
#define QS_M     (OFF_CP + 6800)   // 200*34

// ---------------- device scratch ----------------
__device__ float g_Qg[BN*NN*DD];
__device__ float g_Qm[BN*NN*DD];
__device__ float g_X1[BN*NN*GW];
__device__ float g_X0r[BN*NN*GW];   // [xt | state]
__device__ float g_X0c[BN*NN*GW];   // [xt | rr*state]
__device__ unsigned g_cnt[GROUPS];
__device__ unsigned g_gen[GROUPS];

__device__ __forceinline__ float fsig(float v){
    return __fdividef(1.f, 1.f + __expf(-v));
}

// group-local barrier among the GPB co-resident blocks of one group
__device__ __forceinline__ void group_barrier(int grp){
    __syncthreads();
    if (threadIdx.x == 0){
        volatile unsigned* vg = &g_gen[grp];
        unsigned gen = *vg;
        __threadfence();
        if (atomicAdd(&g_cnt[grp], 1u) == GPB - 1u){
            g_cnt[grp] = 0u;
            __threadfence();
            *vg = gen + 1u;
        } else {
            while (*vg == gen) { }
        }
        __threadfence();
    }
    __syncthreads();
}

// ---- gru for own rows (warp per local row); writes Q global, P smem, sd smem --
__device__ __forceinline__ void gru_step(float* sb, int b, int row0, int nrows, int t,
    const float* __restrict__ x,
    const float* __restrict__ W_rz, const float* __restrict__ b_rz,
    const float* __restrict__ W_h,  const float* __restrict__ b_h,
    const float* __restrict__ Wc2,  const float* __restrict__ bc2,
    const float* __restrict__ Wm2,  const float* __restrict__ bm2)
{
    int warp = threadIdx.x >> 5, lane = threadIdx.x & 31;
    if (warp < nrows){
        int n  = row0 + warp;
        int gi = b*NN + n;
        float* sdp = sb + OFF_SD  + warp*32;
        float* sc  = sb + OFF_GRU + warp*96;   // rs[32] | sv[32]
        const float* xr = x + ((b*TT + t)*NN + n)*CIN;
        if (lane < CIN){
            float xv = xr[lane];
            g_X0r[gi*GW + lane] = xv;
            g_X0c[gi*GW + lane] = xv;
        }
        float inp1 = __ldg(&xr[0]);
        float sdv  = sdp[lane];
        float accr = b_rz[lane]      + inp1 * W_rz[lane];
        float accz = b_rz[lane + 32] + inp1 * W_rz[lane + 32];
        #pragma unroll
        for (int d = 0; d < 32; d++){
            float v = sdp[d];
            accr = fmaf(v, W_rz[(1 + d)*64 + lane],      accr);
            accz = fmaf(v, W_rz[(1 + d)*64 + lane + 32], accz);
        }
        float r = fsig(accr), z = fsig(accz);
        sc[lane] = r * sdv;
        __syncwarp();
        float acch = b_h[lane] + inp1 * W_h[lane];
        #pragma unroll
        for (int d = 0; d < 32; d++) acch = fmaf(sc[d], W_h[(1 + d)*32 + lane], acch);
        float h  = tanhf(acch);
        float nd = z * sdv + (1.f - z) * h;
        sdp[lane] = nd;
        float s = fmaxf(nd, 0.f);
        sc[32 + lane] = s;
        __syncwarp();
        float pg = 0.f, qg = bc2[lane], pm = 0.f, qm = bm2[lane];
        #pragma unroll
        for (int d = 0; d < 32; d++){
            float v = sc[32 + d];
            pg = fmaf(v, Wc2[d*32 + lane],        pg);
            qg = fmaf(v, Wc2[(32 + d)*32 + lane], qg);
            pm = fmaf(v, Wm2[d*32 + lane],        pm);
            qm = fmaf(v, Wm2[(32 + d)*32 + lane], qm);
        }
        sb[OFF_P +       warp*32 + lane] = pg;
        sb[OFF_P + 384 + warp*32 + lane] = pm;
        g_Qg[gi*DD + lane] = qg;
        g_Qm[gi*DD + lane] = qm;
    }
}

// ---- split-K core: acc rows (<=12) of A_smem @ M(200xGW, global) -> Cp smem --
__device__ __forceinline__ void spmm_partials(float* sb, const float* __restrict__ M,
                                              int b, int tid)
{
    if (tid < 825){
        int jg = tid/33, c2 = tid - jg*33;
        int j0 = jg*8;
        const float* Mb = M + b*NN*GW + 2*c2;
        float2 acc[MAXR];
        #pragma unroll
        for (int il = 0; il < MAXR; il++){ acc[il].x = 0.f; acc[il].y = 0.f; }
        #pragma unroll
        for (int jp = 0; jp < 4; jp++){
            int j = j0 + 2*jp;
            float2 x0 = __ldg((const float2*)&Mb[j*GW]);
            float2 x1 = __ldg((const float2*)&Mb[(j+1)*GW]);
            #pragma unroll
            for (int il = 0; il < MAXR; il++){
                float2 a = *(const float2*)&sb[OFF_A + il*200 + j];
                acc[il].x = fmaf(a.x, x0.x, acc[il].x);
                acc[il].y = fmaf(a.x, x0.y, acc[il].y);
                acc[il].x = fmaf(a.y, x1.x, acc[il].x);
                acc[il].y = fmaf(a.y, x1.y, acc[il].y);
            }
        }
        #pragma unroll
        for (int il = 0; il < MAXR; il++)
            *(float2*)&sb[OFF_CP + (jg*MAXR + il)*66 + 2*c2] = acc[il];
    }
}

// ---- hop: X1 rows = A_smem @ X0 ----
__device__ __forceinline__ void hop_phase(float* sb, int b, int row0, int nrows, int tid,
                                          const float* __restrict__ X0)
{
    spmm_partials(sb, X0, b, tid);
    __syncthreads();
    for (int e = tid; e < nrows*GW; e += NTH){
        int il = e/GW, c = e - il*GW;
        float s = 0.f;
        #pragma unroll
        for (int g = 0; g < 25; g++) s += sb[OFF_CP + (g*MAXR + il)*66 + c];
        g_X1[(b*NN + row0 + il)*GW + c] = s;
    }
}

// ---- conv: X2 = A_smem@X1 ; Z=[X0|X1|X2] @ W + act + epilogue ----
template<int FOUT, int CAND>
__device__ __forceinline__ void conv_phase(float* sb, int b, int row0, int nrows, int tid,
                                           const float* __restrict__ W,
                                           const float* __restrict__ bias)
{
    const float* __restrict__ X0 = CAND ? g_X0c : g_X0r;
    spmm_partials(sb, g_X1, b, tid);
    __syncthreads();
    for (int e = tid; e < nrows*GW; e += NTH){
        int il = e/GW, c = e - il*GW;
        float s = 0.f;
        #pragma unroll
        for (int g = 0; g < 25; g++) s += sb[OFF_CP + (g*MAXR + il)*66 + c];
        int row = (b*NN + row0 + il)*GW + c;
        sb[OFF_Z + il*GIN + 2*GW + c] = s;            // X2
        sb[OFF_Z + il*GIN +   GW + c] = g_X1[row];    // X1
        sb[OFF_Z + il*GIN +        c] = X0[row];      // X0
    }
    __syncthreads();
    constexpr int NF4 = FOUT/4;            // 32 or 16
    constexpr int QQ  = (FOUT == 128) ? 2 : 1;
    constexpr int NT  = NF4 * (MAXR/QQ);   // 192
    if (tid < NT){
        int f4  = tid % NF4;
        int il0 = (tid / NF4)*QQ;
        const float4* Wv = (const float4*)W;
        float4 bb = ((const float4*)bias)[f4];
        float4 acc[QQ];
        #pragma unroll
        for (int q = 0; q < QQ; q++) acc[q] = bb;
        #pragma unroll 2
        for (int k = 0; k < GIN; k++){
            float4 w = __ldg(&Wv[k*NF4 + f4]);
            #pragma unroll
            for (int q = 0; q < QQ; q++){
                float zv = sb[OFF_Z + (il0 + q)*GIN + k];
                acc[q].x = fmaf(zv, w.x, acc[q].x);
                acc[q].y = fmaf(zv, w.y, acc[q].y);
                acc[q].z = fmaf(zv, w.z, acc[q].z);
                acc[q].w = fmaf(zv, w.w, acc[q].w);
            }
        }
        #pragma unroll
        for (int q = 0; q < QQ; q++){
            int il = il0 + q;
            if (il < nrows){
                int gi = b*NN + row0 + il;
                float av[4] = {acc[q].x, acc[q].y, acc[q].z, acc[q].w};
                #pragma unroll
                for (int c = 0; c < 4; c++){
                    int f = 4*f4 + c;
                    float a = av[c];
                    if (!CAND){
                        float rv = fsig(a);
                        if (f < HH){
                            float so = g_X0r[gi*GW + CIN + f];
                            g_X0c[gi*GW + CIN + f] = rv * so;
                        } else {
                            sb[OFF_U + il*HH + (f - HH)] = rv;
                        }
                    } else {
                        float cv = tanhf(a);
                        float u  = sb[OFF_U + il*HH + f];
                        float so = g_X0r[gi*GW + CIN + f];
                        g_X0r[gi*GW + CIN + f] = u*so + (1.f - u)*cv;
                    }
                }
            }
        }
    }
}

// ============================ megakernel =====================================
__global__ void __launch_bounds__(NTH, 1) mega_kernel(
    const float* __restrict__ x,     const float* __restrict__ nf,
    const float* __restrict__ W_s2d, const float* __restrict__ b_s2d,
    const float* __restrict__ W_rz,  const float* __restrict__ b_rz,
    const float* __restrict__ W_h,   const float* __restrict__ b_h,
    const float* __restrict__ Wc2,   const float* __restrict__ bc2,
    const float* __restrict__ Wc1,   const float* __restrict__ bc1,
    const float* __restrict__ Wm2,   const float* __restrict__ bm2,
    const float* __restrict__ Wm1,   const float* __restrict__ bm1,
    const float* __restrict__ W_ru,  const float* __restrict__ b_ru,
    const float* __restrict__ W_cand,const float* __restrict__ b_cand,
    const float* __restrict__ Wp1,   const float* __restrict__ bp1,
    const float* __restrict__ Wp2,   const float* __restrict__ bp2,
    float* __restrict__ out_pred,    float* __restrict__ out_dy)
{
    extern __shared__ float sb[];
    int bid = blockIdx.x, tid = threadIdx.x;
    int grp = bid / GPB, rk = bid - grp*GPB;
    int b = grp;
    int warp = tid >> 5, lane = tid & 31;
    int row0  = rk*11 + (rk < 2 ? rk : 2);
    int nrows = 11 + (rk < 2 ? 1 : 0);

    // ---------------- init: state_dy (smem) + zero X0r state cols ----------------
    for (int e = tid; e < nrows*DD; e += NTH){
        int l = e/DD, d = e - l*DD;
        int n = row0 + l;
        float acc = b_s2d[d];
        #pragma unroll 8
        for (int k = 0; k < HST; k++) acc = fmaf(nf[n*HST + k], W_s2d[k*DD + d], acc);
        sb[OFF_SD + l*DD + d] = acc;
    }
    for (int e = tid; e < nrows*HH; e += NTH){
        int l = e/HH, f = e - l*HH;
        g_X0r[(b*NN + row0 + l)*GW + CIN + f] = 0.f;
    }
    if (tid < 32) sb[OFF_W + tid] = Wc1[tid];
    else if (tid < 64) sb[OFF_W + tid] = Wm1[tid - 32];
    __syncthreads();
    gru_step(sb, b, row0, nrows, 0, x, W_rz, b_rz, W_h, b_h, Wc2, bc2, Wm2, bm2);
    group_barrier(grp);

    float bc1v = __ldg(&bc1[0]), bm1v = __ldg(&bm1[0]);

    for (int t = 0; t < TT; t++){
        // -------- phase 1: pair (A rows -> smem + out_dy) then hop_r --------
        {
            // stage Q into smem
            for (int e = tid; e < NN*DD; e += NTH){
                int j = e >> 5, d = e & 31;
                sb[QS_G + j*34 + d] = g_Qg[b*NN*DD + e];
                sb[QS_M + j*34 + d] = g_Qm[b*NN*DD + e];
            }
            __syncthreads();
            if (tid < 800){
                int j  = tid % 200;
                int ig = tid / 200;         // 0..3, each 3 local rows
                float ga[3] = {bc1v, bc1v, bc1v};
                float ma[3] = {bm1v, bm1v, bm1v};
                #pragma unroll
                for (int dp = 0; dp < 16; dp++){
                    float2 qg = *(const float2*)&sb[QS_G + j*34 + 2*dp];
                    float2 qm = *(const float2*)&sb[QS_M + j*34 + 2*dp];
                    float2 wg = *(const float2*)&sb[OFF_W + 2*dp];
                    float2 wm = *(const float2*)&sb[OFF_W + 32 + 2*dp];
                    #pragma unroll
                    for (int q = 0; q < 3; q++){
                        int l = ig*3 + q;
                        float2 pg = *(const float2*)&sb[OFF_P +       l*32 + 2*dp];
                        float2 pm = *(const float2*)&sb[OFF_P + 384 + l*32 + 2*dp];
                        ga[q] = fmaf(fmaxf(pg.x + qg.x, 0.f), wg.x, ga[q]);
                        ga[q] = fmaf(fmaxf(pg.y + qg.y, 0.f), wg.y, ga[q]);
                        ma[q] = fmaf(fmaxf(pm.x + qm.x, 0.f), wm.x, ma[q]);
                        ma[q] = fmaf(fmaxf(pm.y + qm.y, 0.f), wm.y, ma[q]);
                    }
                }
                #pragma unroll
                for (int q = 0; q < 3; q++){
                    int l = ig*3 + q;
                    if (l < nrows){
                        float A = ga[q] * fsig(ma[q]);
                        sb[OFF_A + l*200 + j] = A;
                        out_dy[(((size_t)t*BN + b)*NN + row0 + l)*NN + j] = A;
                    }
                }
            }
            __syncthreads();
            hop_phase(sb, b, row0, nrows, tid, g_X0r);
        }
        group_barrier(grp);

        conv_phase<128, 0>(sb, b, row0, nrows, tid, W_ru, b_ru);
        group_barrier(grp);

        hop_phase(sb, b, row0, nrows, tid, g_X0c);
        group_barrier(grp);

        conv_phase<64, 1>(sb, b, row0, nrows, tid, W_cand, b_cand);
        if (t < TT-1){
            __syncthreads();
            gru_step(sb, b, row0, nrows, t+1, x, W_rz, b_rz, W_h, b_h, Wc2, bc2, Wm2, bm2);
        }
        group_barrier(grp);
    }

    // ---------------- prediction head (own rows; no barrier needed) -------------
    if (warp < nrows){
        int gi = b*NN + row0 + warp;
        float s0 = g_X0r[gi*GW + CIN + lane];
        float s1 = g_X0r[gi*GW + CIN + 32 + lane];
        float a0 = bp1[lane], a1 = bp1[lane + 32];
        #pragma unroll
        for (int k = 0; k < 32; k++){
            float sk = __shfl_sync(0xffffffffu, s0, k);
            a0 = fmaf(sk, Wp1[k*HH + lane],      a0);
            a1 = fmaf(sk, Wp1[k*HH + lane + 32], a1);
        }
        #pragma unroll
        for (int k = 0; k < 32; k++){
            float sk = __shfl_sync(0xffffffffu, s1, k);
            a0 = fmaf(sk, Wp1[(32 + k)*HH + lane],      a0);
            a1 = fmaf(sk, Wp1[(32 + k)*HH + lane + 32], a1);
        }
        float h0 = a0 > 0.f ? a0 : 0.01f*a0;
        float h1 = a1 > 0.f ? a1 : 0.01f*a1;
        float r = h0*Wp2[lane] + h1*Wp2[lane + 32];
        #pragma unroll
        for (int off = 16; off > 0; off >>= 1) r += __shfl_down_sync(0xffffffffu, r, off);
        if (lane == 0) out_pred[gi] = r + bp2[0];
    }
}

// ---------------- launch ------------------------------------------------------
extern "C" void kernel_launch(void* const* d_in, const int* in_sizes, int n_in,
                              void* d_out, int out_size)
{
    (void)in_sizes; (void)n_in; (void)out_size;
    const float* x        = (const float*)d_in[0];
    const float* nf       = (const float*)d_in[1];
    const float* W_s2d    = (const float*)d_in[2];
    const float* b_s2d    = (const float*)d_in[3];
    const float* W_rz     = (const float*)d_in[4];
    const float* b_rz     = (const float*)d_in[5];
    const float* W_h      = (const float*)d_in[6];
    const float* b_h      = (const float*)d_in[7];
    const float* Wc2      = (const float*)d_in[8];
    const float* bc2      = (const float*)d_in[9];
    const float* Wc1      = (const float*)d_in[10];
    const float* bc1      = (const float*)d_in[11];
    const float* Wm2      = (const float*)d_in[12];
    const float* bm2      = (const float*)d_in[13];
    const float* Wm1      = (const float*)d_in[14];
    const float* bm1      = (const float*)d_in[15];
    const float* W_ru     = (const float*)d_in[16];
    const float* b_ru     = (const float*)d_in[17];
    const float* W_cand   = (const float*)d_in[18];
    const float* b_cand   = (const float*)d_in[19];
    const float* Wp1      = (const float*)d_in[20];
    const float* bp1      = (const float*)d_in[21];
    const float* Wp2      = (const float*)d_in[22];
    const float* bp2      = (const float*)d_in[23];

    float* out      = (float*)d_out;
    float* out_pred = out;                 // (B,N,1) = 1600 floats
    float* out_dy   = out + BN*NN;         // (T,B,N,N)

    const int SMEM_BYTES = SMEMF * 4;      // 110848
    cudaFuncSetAttribute(mega_kernel, cudaFuncAttributeMaxDynamicSharedMemorySize, SMEM_BYTES);

    mega_kernel<<<GRID, NTH, SMEM_BYTES>>>(x, nf, W_s2d, b_s2d, W_rz, b_rz, W_h, b_h,
                                           Wc2, bc2, Wc1, bc1, Wm2, bm2, Wm1, bm1,
                                           W_ru, b_ru, W_cand, b_cand,
                                           Wp1, bp1, Wp2, bp2, out_pred, out_dy);
}

// round 11
// speedup vs baseline: 1.5092x; 1.5092x over previous
#include <cuda_runtime.h>
#include <math.h>

#define BN   8
#define TT   12
#define NN   200
#define CIN  2
#define HH   64
#define DD   32
#define HST  64
#define GW   66      // CIN + HH
#define GIN  198     // GW * 3
#define GROUPS 8
#define GPB    18
#define GRID   (GROUPS*GPB)   // 144 blocks, <=148 SMs, all co-resident
#define NTH    1024
#define MAXR   12

// ---- smem layout (floats) ----
#define OFF_A    0          // A tile: 12*200 = 2400
#define OFF_P    2400       // Pg 12*32, Pm 12*32 = 768
#define OFF_SD   3168       // state_dy 12*32 = 384
#define OFF_U    3552       // u 12*64 = 768
#define OFF_W    4320       // wc1 32 | wm1 32
#define OFF_GRU  4384       // gru scratch 12 warps * 96 = 1152
#define OFF_CP   5536       // split-K partials 25*12*66 = 19800 (also Q stage, GEMM partials)
#define OFF_Z    25336      // Z 12*198 = 2376
#define SMEMF    27712      // *4 = 110848 bytes
#define QS_G     OFF_CP
#define QS_M     (OFF_CP + 6600)   // 200*33 each

// ---------------- device scratch ----------------
__device__ float g_Qg[BN*NN*DD];
__device__ float g_Qm[BN*NN*DD];
__device__ float g_X1[BN*NN*GW];
__device__ float g_X0r[BN*NN*GW];   // [xt | state]
__device__ float g_X0c[BN*NN*GW];   // [xt | rr*state]
__device__ unsigned g_cnt[GROUPS];
__device__ unsigned g_gen[GROUPS];

__device__ __forceinline__ float fsig(float v){
    return __fdividef(1.f, 1.f + __expf(-v));
}

// group-local barrier among the GPB co-resident blocks of one group
__device__ __forceinline__ void group_barrier(int grp){
    __syncthreads();
    if (threadIdx.x == 0){
        volatile unsigned* vg = &g_gen[grp];
        unsigned gen = *vg;
        __threadfence();
        if (atomicAdd(&g_cnt[grp], 1u) == GPB - 1u){
            g_cnt[grp] = 0u;
            __threadfence();
            *vg = gen + 1u;
        } else {
            while (*vg == gen) { }
        }
        __threadfence();
    }
    __syncthreads();
}

// ---- gru for own rows (warp per local row) ----
__device__ __forceinline__ void gru_step(float* sb, int b, int row0, int nrows, int t,
    const float* __restrict__ x,
    const float* __restrict__ W_rz, const float* __restrict__ b_rz,
    const float* __restrict__ W_h,  const float* __restrict__ b_h,
    const float* __restrict__ Wc2,  const float* __restrict__ bc2,
    const float* __restrict__ Wm2,  const float* __restrict__ bm2)
{
    int warp = threadIdx.x >> 5, lane = threadIdx.x & 31;
    if (warp < nrows){
        int n  = row0 + warp;
        int gi = b*NN + n;
        float* sdp = sb + OFF_SD  + warp*32;
        float* sc  = sb + OFF_GRU + warp*96;   // rs[32] | sv[32]
        const float* xr = x + ((b*TT + t)*NN + n)*CIN;
        if (lane < CIN){
            float xv = xr[lane];
            g_X0r[gi*GW + lane] = xv;
            g_X0c[gi*GW + lane] = xv;
        }
        float inp1 = __ldg(&xr[0]);
        float sdv  = sdp[lane];
        float accr = b_rz[lane]      + inp1 * W_rz[lane];
        float accz = b_rz[lane + 32] + inp1 * W_rz[lane + 32];
        #pragma unroll
        for (int d = 0; d < 32; d++){
            float v = sdp[d];
            accr = fmaf(v, W_rz[(1 + d)*64 + lane],      accr);
            accz = fmaf(v, W_rz[(1 + d)*64 + lane + 32], accz);
        }
        float r = fsig(accr), z = fsig(accz);
        sc[lane] = r * sdv;
        __syncwarp();
        float acch = b_h[lane] + inp1 * W_h[lane];
        #pragma unroll
        for (int d = 0; d < 32; d++) acch = fmaf(sc[d], W_h[(1 + d)*32 + lane], acch);
        float h  = tanhf(acch);
        float nd = z * sdv + (1.f - z) * h;
        sdp[lane] = nd;
        float s = fmaxf(nd, 0.f);
        sc[32 + lane] = s;
        __syncwarp();
        float pg = 0.f, qg = bc2[lane], pm = 0.f, qm = bm2[lane];
        #pragma unroll
        for (int d = 0; d < 32; d++){
            float v = sc[32 + d];
            pg = fmaf(v, Wc2[d*32 + lane],        pg);
            qg = fmaf(v, Wc2[(32 + d)*32 + lane], qg);
            pm = fmaf(v, Wm2[d*32 + lane],        pm);
            qm = fmaf(v, Wm2[(32 + d)*32 + lane], qm);
        }
        sb[OFF_P +       warp*32 + lane] = pg;
        sb[OFF_P + 384 + warp*32 + lane] = pm;
        g_Qg[gi*DD + lane] = qg;
        g_Qm[gi*DD + lane] = qm;
    }
}

// ---- split-K core: own rows of A_smem @ M(200xGW, global) -> Cp smem ----
__device__ __forceinline__ void spmm_partials(float* sb, const float* __restrict__ M,
                                              int b, int tid)
{
    if (tid < 825){
        int jg = tid/33, c2 = tid - jg*33;
        int j0 = jg*8;
        const float* Mb = M + b*NN*GW + 2*c2;
        float2 acc[MAXR];
        #pragma unroll
        for (int il = 0; il < MAXR; il++){ acc[il].x = 0.f; acc[il].y = 0.f; }
        #pragma unroll
        for (int jp = 0; jp < 4; jp++){
            int j = j0 + 2*jp;
            float2 x0 = __ldg((const float2*)&Mb[j*GW]);
            float2 x1 = __ldg((const float2*)&Mb[(j+1)*GW]);
            #pragma unroll
            for (int il = 0; il < MAXR; il++){
                float2 a = *(const float2*)&sb[OFF_A + il*200 + j];
                acc[il].x = fmaf(a.x, x0.x, acc[il].x);
                acc[il].y = fmaf(a.x, x0.y, acc[il].y);
                acc[il].x = fmaf(a.y, x1.x, acc[il].x);
                acc[il].y = fmaf(a.y, x1.y, acc[il].y);
            }
        }
        #pragma unroll
        for (int il = 0; il < MAXR; il++)
            *(float2*)&sb[OFF_CP + (jg*MAXR + il)*66 + 2*c2] = acc[il];
    }
}

// ---- hop: X1 rows = A_smem @ X0 ----
__device__ __forceinline__ void hop_phase(float* sb, int b, int row0, int nrows, int tid,
                                          const float* __restrict__ X0)
{
    spmm_partials(sb, X0, b, tid);
    __syncthreads();
    for (int e = tid; e < nrows*GW; e += NTH){
        int il = e/GW, c = e - il*GW;
        float s = 0.f;
        #pragma unroll
        for (int g = 0; g < 25; g++) s += sb[OFF_CP + (g*MAXR + il)*66 + c];
        g_X1[(b*NN + row0 + il)*GW + c] = s;
    }
}

// ---- conv: X2 = A_smem@X1 ; Z=[X0|X1|X2] @ W (split-K GEMM) + act + epilogue --
template<int FOUT, int CAND>
__device__ __forceinline__ void conv_phase(float* sb, int b, int row0, int nrows, int tid,
                                           const float* __restrict__ W,
                                           const float* __restrict__ bias)
{
    const float* __restrict__ X0 = CAND ? g_X0c : g_X0r;
    spmm_partials(sb, g_X1, b, tid);
    __syncthreads();
    for (int e = tid; e < nrows*GW; e += NTH){
        int il = e/GW, c = e - il*GW;
        float s = 0.f;
        #pragma unroll
        for (int g = 0; g < 25; g++) s += sb[OFF_CP + (g*MAXR + il)*66 + c];
        int row = (b*NN + row0 + il)*GW + c;
        sb[OFF_Z + il*GIN + 2*GW + c] = s;            // X2
        sb[OFF_Z + il*GIN +   GW + c] = g_X1[row];    // X1
        sb[OFF_Z + il*GIN +        c] = X0[row];      // X0
    }
    __syncthreads();
    // split-K GEMM: KG k-chunks, each (FOUT/4 f-quads) x 12 rows
    constexpr int NF4 = FOUT/4;            // 32 or 16
    constexpr int KG  = (FOUT == 128) ? 2 : 4;
    constexpr int NT  = NF4 * MAXR * KG;   // 768
    if (tid < NT){
        int f4 = tid % NF4;
        int il = (tid / NF4) % MAXR;
        int kg = tid / (NF4*MAXR);
        int kc0, klen;
        if (FOUT == 128){ kc0 = kg*99; klen = 99; }
        else { kc0 = kg*50 - (kg > 2 ? kg - 2 : 0); klen = (kg < 2) ? 50 : 49; }
        const float4* Wv = (const float4*)W;
        float4 acc; acc.x = 0.f; acc.y = 0.f; acc.z = 0.f; acc.w = 0.f;
        const float* zr = sb + OFF_Z + il*GIN;
        #pragma unroll 2
        for (int k = kc0; k < kc0 + klen; k++){
            float4 w = __ldg(&Wv[k*NF4 + f4]);
            float zv = zr[k];
            acc.x = fmaf(zv, w.x, acc.x);
            acc.y = fmaf(zv, w.y, acc.y);
            acc.z = fmaf(zv, w.z, acc.z);
            acc.w = fmaf(zv, w.w, acc.w);
        }
        *(float4*)&sb[OFF_CP + (kg*MAXR + il)*FOUT + 4*f4] = acc;
    }
    __syncthreads();
    // reduce partials + bias + activation + epilogue
    for (int e = tid; e < MAXR*FOUT; e += NTH){
        int il = e / FOUT, f = e - il*FOUT;
        float s = __ldg(&bias[f]);
        #pragma unroll
        for (int g = 0; g < KG; g++) s += sb[OFF_CP + (g*MAXR + il)*FOUT + f];
        if (il < nrows){
            int gi = b*NN + row0 + il;
            if (!CAND){
                float rv = fsig(s);
                if (f < HH) g_X0c[gi*GW + CIN + f] = rv * g_X0r[gi*GW + CIN + f];
                else        sb[OFF_U + il*HH + (f - HH)] = rv;
            } else {
                float cv = tanhf(s);
                float u  = sb[OFF_U + il*HH + f];
                float so = g_X0r[gi*GW + CIN + f];
                g_X0r[gi*GW + CIN + f] = u*so + (1.f - u)*cv;
            }
        }
    }
}

// ============================ megakernel =====================================
__global__ void __launch_bounds__(NTH, 1) mega_kernel(
    const float* __restrict__ x,     const float* __restrict__ nf,
    const float* __restrict__ W_s2d, const float* __restrict__ b_s2d,
    const float* __restrict__ W_rz,  const float* __restrict__ b_rz,
    const float* __restrict__ W_h,   const float* __restrict__ b_h,
    const float* __restrict__ Wc2,   const float* __restrict__ bc2,
    const float* __restrict__ Wc1,   const float* __restrict__ bc1,
    const float* __restrict__ Wm2,   const float* __restrict__ bm2,
    const float* __restrict__ Wm1,   const float* __restrict__ bm1,
    const float* __restrict__ W_ru,  const float* __restrict__ b_ru,
    const float* __restrict__ W_cand,const float* __restrict__ b_cand,
    const float* __restrict__ Wp1,   const float* __restrict__ bp1,
    const float* __restrict__ Wp2,   const float* __restrict__ bp2,
    float* __restrict__ out_pred,    float* __restrict__ out_dy)
{
    extern __shared__ float sb[];
    int bid = blockIdx.x, tid = threadIdx.x;
    int grp = bid / GPB, rk = bid - grp*GPB;
    int b = grp;
    int warp = tid >> 5, lane = tid & 31;
    int row0  = rk*11 + (rk < 2 ? rk : 2);
    int nrows = 11 + (rk < 2 ? 1 : 0);

    // ---------------- init ----------------
    for (int e = tid; e < nrows*DD; e += NTH){
        int l = e/DD, d = e - l*DD;
        int n = row0 + l;
        float acc = b_s2d[d];
        #pragma unroll 8
        for (int k = 0; k < HST; k++) acc = fmaf(nf[n*HST + k], W_s2d[k*DD + d], acc);
        sb[OFF_SD + l*DD + d] = acc;
    }
    for (int e = tid; e < nrows*HH; e += NTH){
        int l = e/HH, f = e - l*HH;
        g_X0r[(b*NN + row0 + l)*GW + CIN + f] = 0.f;
    }
    if (tid < 32) sb[OFF_W + tid] = Wc1[tid];
    else if (tid < 64) sb[OFF_W + tid] = Wm1[tid - 32];
    __syncthreads();
    gru_step(sb, b, row0, nrows, 0, x, W_rz, b_rz, W_h, b_h, Wc2, bc2, Wm2, bm2);
    group_barrier(grp);

    float bc1v = __ldg(&bc1[0]), bm1v = __ldg(&bm1[0]);

    for (int t = 0; t < TT; t++){
        // -------- phase 1: pair (A rows -> smem + out_dy) then hop_r --------
        {
            // stage Q into smem at stride 33 (conflict-free store & load)
            for (int e = tid; e < NN*DD; e += NTH){
                int j = e >> 5, d = e & 31;
                sb[QS_G + j*33 + d] = g_Qg[b*NN*DD + e];
                sb[QS_M + j*33 + d] = g_Qm[b*NN*DD + e];
            }
            __syncthreads();
            if (tid < 800){
                int j  = tid % 200;
                int ig = tid / 200;         // 0..3, each 3 local rows
                float ga[3] = {bc1v, bc1v, bc1v};
                float ma[3] = {bm1v, bm1v, bm1v};
                const float* qgp = sb + QS_G + j*33;
                const float* qmp = sb + QS_M + j*33;
                #pragma unroll 4
                for (int d = 0; d < 32; d++){
                    float qg = qgp[d], qm = qmp[d];
                    float wg = sb[OFF_W + d], wm = sb[OFF_W + 32 + d];
                    #pragma unroll
                    for (int q = 0; q < 3; q++){
                        int l = ig*3 + q;
                        float pg = sb[OFF_P +       l*32 + d];
                        float pm = sb[OFF_P + 384 + l*32 + d];
                        ga[q] = fmaf(fmaxf(pg + qg, 0.f), wg, ga[q]);
                        ma[q] = fmaf(fmaxf(pm + qm, 0.f), wm, ma[q]);
                    }
                }
                #pragma unroll
                for (int q = 0; q < 3; q++){
                    int l = ig*3 + q;
                    if (l < nrows){
                        float A = ga[q] * fsig(ma[q]);
                        sb[OFF_A + l*200 + j] = A;
                        out_dy[(((size_t)t*BN + b)*NN + row0 + l)*NN + j] = A;
                    }
                }
            }
            __syncthreads();
            hop_phase(sb, b, row0, nrows, tid, g_X0r);
        }
        group_barrier(grp);

        conv_phase<128, 0>(sb, b, row0, nrows, tid, W_ru, b_ru);
        group_barrier(grp);

        hop_phase(sb, b, row0, nrows, tid, g_X0c);
        group_barrier(grp);

        conv_phase<64, 1>(sb, b, row0, nrows, tid, W_cand, b_cand);
        if (t < TT-1){
            __syncthreads();
            gru_step(sb, b, row0, nrows, t+1, x, W_rz, b_rz, W_h, b_h, Wc2, bc2, Wm2, bm2);
        }
        group_barrier(grp);
    }

    // ---------------- prediction head (own rows; no barrier needed) -------------
    if (warp < nrows){
        int gi = b*NN + row0 + warp;
        float s0 = g_X0r[gi*GW + CIN + lane];
        float s1 = g_X0r[gi*GW + CIN + 32 + lane];
        float a0 = bp1[lane], a1 = bp1[lane + 32];
        #pragma unroll
        for (int k = 0; k < 32; k++){
            float sk = __shfl_sync(0xffffffffu, s0, k);
            a0 = fmaf(sk, Wp1[k*HH + lane],      a0);
            a1 = fmaf(sk, Wp1[k*HH + lane + 32], a1);
        }
        #pragma unroll
        for (int k = 0; k < 32; k++){
            float sk = __shfl_sync(0xffffffffu, s1, k);
            a0 = fmaf(sk, Wp1[(32 + k)*HH + lane],      a0);
            a1 = fmaf(sk, Wp1[(32 + k)*HH + lane + 32], a1);
        }
        float h0 = a0 > 0.f ? a0 : 0.01f*a0;
        float h1 = a1 > 0.f ? a1 : 0.01f*a1;
        float r = h0*Wp2[lane] + h1*Wp2[lane + 32];
        #pragma unroll
        for (int off = 16; off > 0; off >>= 1) r += __shfl_down_sync(0xffffffffu, r, off);
        if (lane == 0) out_pred[gi] = r + bp2[0];
    }
}

// ---------------- launch ------------------------------------------------------
extern "C" void kernel_launch(void* const* d_in, const int* in_sizes, int n_in,
                              void* d_out, int out_size)
{
    (void)in_sizes; (void)n_in; (void)out_size;
    const float* x        = (const float*)d_in[0];
    const float* nf       = (const float*)d_in[1];
    const float* W_s2d    = (const float*)d_in[2];
    const float* b_s2d    = (const float*)d_in[3];
    const float* W_rz     = (const float*)d_in[4];
    const float* b_rz     = (const float*)d_in[5];
    const float* W_h      = (const float*)d_in[6];
    const float* b_h      = (const float*)d_in[7];
    const float* Wc2      = (const float*)d_in[8];
    const float* bc2      = (const float*)d_in[9];
    const float* Wc1      = (const float*)d_in[10];
    const float* bc1      = (const float*)d_in[11];
    const float* Wm2      = (const float*)d_in[12];
    const float* bm2      = (const float*)d_in[13];
    const float* Wm1      = (const float*)d_in[14];
    const float* bm1      = (const float*)d_in[15];
    const float* W_ru     = (const float*)d_in[16];
    const float* b_ru     = (const float*)d_in[17];
    const float* W_cand   = (const float*)d_in[18];
    const float* b_cand   = (const float*)d_in[19];
    const float* Wp1      = (const float*)d_in[20];
    const float* bp1      = (const float*)d_in[21];
    const float* Wp2      = (const float*)d_in[22];
    const float* bp2      = (const float*)d_in[23];

    float* out      = (float*)d_out;
    float* out_pred = out;                 // (B,N,1) = 1600 floats
    float* out_dy   = out + BN*NN;         // (T,B,N,N)

    const int SMEM_BYTES = SMEMF * 4;      // 110848
    cudaFuncSetAttribute(mega_kernel, cudaFuncAttributeMaxDynamicSharedMemorySize, SMEM_BYTES);

    mega_kernel<<<GRID, NTH, SMEM_BYTES>>>(x, nf, W_s2d, b_s2d, W_rz, b_rz, W_h, b_h,
                                           Wc2, bc2, Wc1, bc1, Wm2, bm2, Wm1, bm1,
                                           W_ru, b_ru, W_cand, b_cand,
                                           Wp1, bp1, Wp2, bp2, out_pred, out_dy);
}

// round 12
// speedup vs baseline: 1.5122x; 1.0020x over previous
#include <cuda_runtime.h>
#include <math.h>

#define BN   8
#define TT   12
#define NN   200
#define CIN  2
#define HH   64
#define DD   32
#define HST  64
#define GW   66      // CIN + HH
#define GIN  198     // GW * 3
#define GROUPS 8
#define GPB    18
#define GRID   (GROUPS*GPB)   // 144 blocks, <=148 SMs, all co-resident
#define NTH    1024
#define MAXR   12

// ---- smem layout (floats) ----
#define OFF_A    0          // A tile: 12*200 = 2400
#define OFF_P    2400       // Pg 12*32, Pm 12*32 = 768
#define OFF_SD   3168       // state_dy 12*32 = 384
#define OFF_U    3552       // u 12*64 = 768
#define OFF_W    4320       // wc1 32 | wm1 32
#define OFF_GRU  4384       // gru scratch 12 warps * 96 = 1152
#define OFF_CP   5536       // split-K partials 25*12*66 = 19800 (also Q stage, GEMM partials)
#define OFF_Z    25336      // Z 12*198 = 2376
#define SMEMF    27712      // *4 = 110848 bytes
#define QS_G     OFF_CP                  // 200*36 = 7200
#define QS_M     (OFF_CP + 7200)         // 200*36 = 7200

// ---------------- device scratch ----------------
__device__ float g_Qg[BN*NN*DD];
__device__ float g_Qm[BN*NN*DD];
__device__ float g_X1[BN*NN*GW];
__device__ float g_X0r[BN*NN*GW];   // [xt | state]
__device__ float g_X0c[BN*NN*GW];   // [xt | rr*state]
__device__ unsigned g_cnt[GROUPS];
__device__ unsigned g_gen[GROUPS];

__device__ __forceinline__ float fsig(float v){
    return __fdividef(1.f, 1.f + __expf(-v));
}

// group-local barrier among the GPB co-resident blocks of one group
__device__ __forceinline__ void group_barrier(int grp){
    __syncthreads();
    if (threadIdx.x == 0){
        volatile unsigned* vg = &g_gen[grp];
        unsigned gen = *vg;
        __threadfence();
        if (atomicAdd(&g_cnt[grp], 1u) == GPB - 1u){
            g_cnt[grp] = 0u;
            __threadfence();
            *vg = gen + 1u;
        } else {
            while (*vg == gen) { }
        }
        __threadfence();
    }
    __syncthreads();
}

// ---- gru for own rows (warp per local row) ----
__device__ __forceinline__ void gru_step(float* sb, int b, int row0, int nrows, int t,
    const float* __restrict__ x,
    const float* __restrict__ W_rz, const float* __restrict__ b_rz,
    const float* __restrict__ W_h,  const float* __restrict__ b_h,
    const float* __restrict__ Wc2,  const float* __restrict__ bc2,
    const float* __restrict__ Wm2,  const float* __restrict__ bm2)
{
    int warp = threadIdx.x >> 5, lane = threadIdx.x & 31;
    if (warp < nrows){
        int n  = row0 + warp;
        int gi = b*NN + n;
        float* sdp = sb + OFF_SD  + warp*32;
        float* sc  = sb + OFF_GRU + warp*96;   // rs[32] | sv[32]
        const float* xr = x + ((b*TT + t)*NN + n)*CIN;
        if (lane < CIN){
            float xv = xr[lane];
            g_X0r[gi*GW + lane] = xv;
            g_X0c[gi*GW + lane] = xv;
        }
        float inp1 = __ldg(&xr[0]);
        float sdv  = sdp[lane];
        float accr = b_rz[lane]      + inp1 * W_rz[lane];
        float accz = b_rz[lane + 32] + inp1 * W_rz[lane + 32];
        #pragma unroll
        for (int d = 0; d < 32; d++){
            float v = sdp[d];
            accr = fmaf(v, W_rz[(1 + d)*64 + lane],      accr);
            accz = fmaf(v, W_rz[(1 + d)*64 + lane + 32], accz);
        }
        float r = fsig(accr), z = fsig(accz);
        sc[lane] = r * sdv;
        __syncwarp();
        float acch = b_h[lane] + inp1 * W_h[lane];
        #pragma unroll
        for (int d = 0; d < 32; d++) acch = fmaf(sc[d], W_h[(1 + d)*32 + lane], acch);
        float h  = tanhf(acch);
        float nd = z * sdv + (1.f - z) * h;
        sdp[lane] = nd;
        float s = fmaxf(nd, 0.f);
        sc[32 + lane] = s;
        __syncwarp();
        float pg = 0.f, qg = bc2[lane], pm = 0.f, qm = bm2[lane];
        #pragma unroll
        for (int d = 0; d < 32; d++){
            float v = sc[32 + d];
            pg = fmaf(v, Wc2[d*32 + lane],        pg);
            qg = fmaf(v, Wc2[(32 + d)*32 + lane], qg);
            pm = fmaf(v, Wm2[d*32 + lane],        pm);
            qm = fmaf(v, Wm2[(32 + d)*32 + lane], qm);
        }
        sb[OFF_P +       warp*32 + lane] = pg;
        sb[OFF_P + 384 + warp*32 + lane] = pm;
        g_Qg[gi*DD + lane] = qg;
        g_Qm[gi*DD + lane] = qm;
    }
}

// ---- split-K core: own rows of A_smem @ M(200xGW, global) -> Cp smem ----
__device__ __forceinline__ void spmm_partials(float* sb, const float* __restrict__ M,
                                              int b, int tid)
{
    if (tid < 825){
        int jg = tid/33, c2 = tid - jg*33;
        int j0 = jg*8;
        const float* Mb = M + b*NN*GW + 2*c2;
        float2 acc[MAXR];
        #pragma unroll
        for (int il = 0; il < MAXR; il++){ acc[il].x = 0.f; acc[il].y = 0.f; }
        #pragma unroll
        for (int jp = 0; jp < 4; jp++){
            int j = j0 + 2*jp;
            float2 x0 = __ldg((const float2*)&Mb[j*GW]);
            float2 x1 = __ldg((const float2*)&Mb[(j+1)*GW]);
            #pragma unroll
            for (int il = 0; il < MAXR; il++){
                float2 a = *(const float2*)&sb[OFF_A + il*200 + j];
                acc[il].x = fmaf(a.x, x0.x, acc[il].x);
                acc[il].y = fmaf(a.x, x0.y, acc[il].y);
                acc[il].x = fmaf(a.y, x1.x, acc[il].x);
                acc[il].y = fmaf(a.y, x1.y, acc[il].y);
            }
        }
        #pragma unroll
        for (int il = 0; il < MAXR; il++)
            *(float2*)&sb[OFF_CP + (jg*MAXR + il)*66 + 2*c2] = acc[il];
    }
}

// ---- hop: X1 rows = A_smem @ X0 ----
__device__ __forceinline__ void hop_phase(float* sb, int b, int row0, int nrows, int tid,
                                          const float* __restrict__ X0)
{
    spmm_partials(sb, X0, b, tid);
    __syncthreads();
    for (int e = tid; e < nrows*GW; e += NTH){
        int il = e/GW, c = e - il*GW;
        float s = 0.f;
        #pragma unroll
        for (int g = 0; g < 25; g++) s += sb[OFF_CP + (g*MAXR + il)*66 + c];
        g_X1[(b*NN + row0 + il)*GW + c] = s;
    }
}

// ---- conv: X2 = A_smem@X1 ; Z=[X0|X1|X2] @ W (il-blocked split-K GEMM) ------
template<int FOUT, int CAND>
__device__ __forceinline__ void conv_phase(float* sb, int b, int row0, int nrows, int tid,
                                           const float* __restrict__ W,
                                           const float* __restrict__ bias)
{
    const float* __restrict__ X0 = CAND ? g_X0c : g_X0r;
    spmm_partials(sb, g_X1, b, tid);
    __syncthreads();
    for (int e = tid; e < nrows*GW; e += NTH){
        int il = e/GW, c = e - il*GW;
        float s = 0.f;
        #pragma unroll
        for (int g = 0; g < 25; g++) s += sb[OFF_CP + (g*MAXR + il)*66 + c];
        int row = (b*NN + row0 + il)*GW + c;
        sb[OFF_Z + il*GIN + 2*GW + c] = s;            // X2
        sb[OFF_Z + il*GIN +   GW + c] = g_X1[row];    // X1
        sb[OFF_Z + il*GIN +        c] = X0[row];      // X0
    }
    __syncthreads();
    // il-blocked split-K GEMM: each thread: 3 il rows x 4 f x k-chunk
    constexpr int NF4 = FOUT/4;            // 32 or 16
    constexpr int KG  = (FOUT == 128) ? 2 : 4;
    constexpr int NT  = NF4 * 4 * KG;      // 256
    if (tid < NT){
        int f4  = tid % NF4;
        int ilg = (tid / NF4) & 3;
        int kg  = tid / (NF4*4);
        int il0 = ilg*3;
        int kc0, klen;
        if (FOUT == 128){ kc0 = kg*99; klen = 99; }
        else { kc0 = kg*50 - (kg > 2 ? kg - 2 : 0); klen = (kg < 2) ? 50 : 49; }
        const float4* Wv = (const float4*)W;
        float4 acc0, acc1, acc2;
        acc0.x=0.f;acc0.y=0.f;acc0.z=0.f;acc0.w=0.f;
        acc1 = acc0; acc2 = acc0;
        const float* z0 = sb + OFF_Z + (il0+0)*GIN;
        const float* z1 = sb + OFF_Z + (il0+1)*GIN;
        const float* z2 = sb + OFF_Z + (il0+2)*GIN;
        #pragma unroll 2
        for (int k = kc0; k < kc0 + klen; k++){
            float4 w = __ldg(&Wv[k*NF4 + f4]);
            float a0 = z0[k], a1 = z1[k], a2 = z2[k];
            acc0.x = fmaf(a0, w.x, acc0.x); acc0.y = fmaf(a0, w.y, acc0.y);
            acc0.z = fmaf(a0, w.z, acc0.z); acc0.w = fmaf(a0, w.w, acc0.w);
            acc1.x = fmaf(a1, w.x, acc1.x); acc1.y = fmaf(a1, w.y, acc1.y);
            acc1.z = fmaf(a1, w.z, acc1.z); acc1.w = fmaf(a1, w.w, acc1.w);
            acc2.x = fmaf(a2, w.x, acc2.x); acc2.y = fmaf(a2, w.y, acc2.y);
            acc2.z = fmaf(a2, w.z, acc2.z); acc2.w = fmaf(a2, w.w, acc2.w);
        }
        *(float4*)&sb[OFF_CP + (kg*MAXR + il0+0)*FOUT + 4*f4] = acc0;
        *(float4*)&sb[OFF_CP + (kg*MAXR + il0+1)*FOUT + 4*f4] = acc1;
        *(float4*)&sb[OFF_CP + (kg*MAXR + il0+2)*FOUT + 4*f4] = acc2;
    }
    __syncthreads();
    // reduce partials + bias + activation + epilogue
    for (int e = tid; e < MAXR*FOUT; e += NTH){
        int il = e / FOUT, f = e - il*FOUT;
        float s = __ldg(&bias[f]);
        #pragma unroll
        for (int g = 0; g < KG; g++) s += sb[OFF_CP + (g*MAXR + il)*FOUT + f];
        if (il < nrows){
            int gi = b*NN + row0 + il;
            if (!CAND){
                float rv = fsig(s);
                if (f < HH) g_X0c[gi*GW + CIN + f] = rv * g_X0r[gi*GW + CIN + f];
                else        sb[OFF_U + il*HH + (f - HH)] = rv;
            } else {
                float cv = tanhf(s);
                float u  = sb[OFF_U + il*HH + f];
                float so = g_X0r[gi*GW + CIN + f];
                g_X0r[gi*GW + CIN + f] = u*so + (1.f - u)*cv;
            }
        }
    }
}

// ============================ megakernel =====================================
__global__ void __launch_bounds__(NTH, 1) mega_kernel(
    const float* __restrict__ x,     const float* __restrict__ nf,
    const float* __restrict__ W_s2d, const float* __restrict__ b_s2d,
    const float* __restrict__ W_rz,  const float* __restrict__ b_rz,
    const float* __restrict__ W_h,   const float* __restrict__ b_h,
    const float* __restrict__ Wc2,   const float* __restrict__ bc2,
    const float* __restrict__ Wc1,   const float* __restrict__ bc1,
    const float* __restrict__ Wm2,   const float* __restrict__ bm2,
    const float* __restrict__ Wm1,   const float* __restrict__ bm1,
    const float* __restrict__ W_ru,  const float* __restrict__ b_ru,
    const float* __restrict__ W_cand,const float* __restrict__ b_cand,
    const float* __restrict__ Wp1,   const float* __restrict__ bp1,
    const float* __restrict__ Wp2,   const float* __restrict__ bp2,
    float* __restrict__ out_pred,    float* __restrict__ out_dy)
{
    extern __shared__ float sb[];
    int bid = blockIdx.x, tid = threadIdx.x;
    int grp = bid / GPB, rk = bid - grp*GPB;
    int b = grp;
    int warp = tid >> 5, lane = tid & 31;
    int row0  = rk*11 + (rk < 2 ? rk : 2);
    int nrows = 11 + (rk < 2 ? 1 : 0);

    // ---------------- init ----------------
    for (int e = tid; e < nrows*DD; e += NTH){
        int l = e/DD, d = e - l*DD;
        int n = row0 + l;
        float acc = b_s2d[d];
        #pragma unroll 8
        for (int k = 0; k < HST; k++) acc = fmaf(nf[n*HST + k], W_s2d[k*DD + d], acc);
        sb[OFF_SD + l*DD + d] = acc;
    }
    for (int e = tid; e < nrows*HH; e += NTH){
        int l = e/HH, f = e - l*HH;
        g_X0r[(b*NN + row0 + l)*GW + CIN + f] = 0.f;
    }
    if (tid < 32) sb[OFF_W + tid] = Wc1[tid];
    else if (tid < 64) sb[OFF_W + tid] = Wm1[tid - 32];
    __syncthreads();
    gru_step(sb, b, row0, nrows, 0, x, W_rz, b_rz, W_h, b_h, Wc2, bc2, Wm2, bm2);
    group_barrier(grp);

    float bc1v = __ldg(&bc1[0]), bm1v = __ldg(&bm1[0]);

    for (int t = 0; t < TT; t++){
        // -------- phase 1: pair (A rows -> smem + out_dy) then hop_r --------
        {
            // stage Q into smem at stride 36 (16B-aligned float4, conflict-free)
            for (int e = tid; e < NN*DD; e += NTH){
                int j = e >> 5, d = e & 31;
                sb[QS_G + j*36 + d] = g_Qg[b*NN*DD + e];
                sb[QS_M + j*36 + d] = g_Qm[b*NN*DD + e];
            }
            __syncthreads();
            if (tid < 800){
                int j  = tid % 200;
                int ig = tid / 200;         // 0..3, each 3 local rows
                float ga[3] = {bc1v, bc1v, bc1v};
                float ma[3] = {bm1v, bm1v, bm1v};
                #pragma unroll
                for (int dc = 0; dc < 32; dc += 4){
                    float4 qg = *(const float4*)&sb[QS_G + j*36 + dc];
                    float4 qm = *(const float4*)&sb[QS_M + j*36 + dc];
                    float4 wg = *(const float4*)&sb[OFF_W + dc];
                    float4 wm = *(const float4*)&sb[OFF_W + 32 + dc];
                    #pragma unroll
                    for (int q = 0; q < 3; q++){
                        int l = ig*3 + q;
                        float4 pg = *(const float4*)&sb[OFF_P +       l*32 + dc];
                        float4 pm = *(const float4*)&sb[OFF_P + 384 + l*32 + dc];
                        ga[q] = fmaf(fmaxf(pg.x + qg.x, 0.f), wg.x, ga[q]);
                        ga[q] = fmaf(fmaxf(pg.y + qg.y, 0.f), wg.y, ga[q]);
                        ga[q] = fmaf(fmaxf(pg.z + qg.z, 0.f), wg.z, ga[q]);
                        ga[q] = fmaf(fmaxf(pg.w + qg.w, 0.f), wg.w, ga[q]);
                        ma[q] = fmaf(fmaxf(pm.x + qm.x, 0.f), wm.x, ma[q]);
                        ma[q] = fmaf(fmaxf(pm.y + qm.y, 0.f), wm.y, ma[q]);
                        ma[q] = fmaf(fmaxf(pm.z + qm.z, 0.f), wm.z, ma[q]);
                        ma[q] = fmaf(fmaxf(pm.w + qm.w, 0.f), wm.w, ma[q]);
                    }
                }
                #pragma unroll
                for (int q = 0; q < 3; q++){
                    int l = ig*3 + q;
                    if (l < nrows){
                        float A = ga[q] * fsig(ma[q]);
                        sb[OFF_A + l*200 + j] = A;
                        out_dy[(((size_t)t*BN + b)*NN + row0 + l)*NN + j] = A;
                    }
                }
            }
            __syncthreads();
            hop_phase(sb, b, row0, nrows, tid, g_X0r);
        }
        group_barrier(grp);

        conv_phase<128, 0>(sb, b, row0, nrows, tid, W_ru, b_ru);
        group_barrier(grp);

        hop_phase(sb, b, row0, nrows, tid, g_X0c);
        group_barrier(grp);

        conv_phase<64, 1>(sb, b, row0, nrows, tid, W_cand, b_cand);
        if (t < TT-1){
            __syncthreads();
            gru_step(sb, b, row0, nrows, t+1, x, W_rz, b_rz, W_h, b_h, Wc2, bc2, Wm2, bm2);
        }
        group_barrier(grp);
    }

    // ---------------- prediction head (own rows; no barrier needed) -------------
    if (warp < nrows){
        int gi = b*NN + row0 + warp;
        float s0 = g_X0r[gi*GW + CIN + lane];
        float s1 = g_X0r[gi*GW + CIN + 32 + lane];
        float a0 = bp1[lane], a1 = bp1[lane + 32];
        #pragma unroll
        for (int k = 0; k < 32; k++){
            float sk = __shfl_sync(0xffffffffu, s0, k);
            a0 = fmaf(sk, Wp1[k*HH + lane],      a0);
            a1 = fmaf(sk, Wp1[k*HH + lane + 32], a1);
        }
        #pragma unroll
        for (int k = 0; k < 32; k++){
            float sk = __shfl_sync(0xffffffffu, s1, k);
            a0 = fmaf(sk, Wp1[(32 + k)*HH + lane],      a0);
            a1 = fmaf(sk, Wp1[(32 + k)*HH + lane + 32], a1);
        }
        float h0 = a0 > 0.f ? a0 : 0.01f*a0;
        float h1 = a1 > 0.f ? a1 : 0.01f*a1;
        float r = h0*Wp2[lane] + h1*Wp2[lane + 32];
        #pragma unroll
        for (int off = 16; off > 0; off >>= 1) r += __shfl_down_sync(0xffffffffu, r, off);
        if (lane == 0) out_pred[gi] = r + bp2[0];
    }
}

// ---------------- launch ------------------------------------------------------
extern "C" void kernel_launch(void* const* d_in, const int* in_sizes, int n_in,
                              void* d_out, int out_size)
{
    (void)in_sizes; (void)n_in; (void)out_size;
    const float* x        = (const float*)d_in[0];
    const float* nf       = (const float*)d_in[1];
    const float* W_s2d    = (const float*)d_in[2];
    const float* b_s2d    = (const float*)d_in[3];
    const float* W_rz     = (const float*)d_in[4];
    const float* b_rz     = (const float*)d_in[5];
    const float* W_h      = (const float*)d_in[6];
    const float* b_h      = (const float*)d_in[7];
    const float* Wc2      = (const float*)d_in[8];
    const float* bc2      = (const float*)d_in[9];
    const float* Wc1      = (const float*)d_in[10];
    const float* bc1      = (const float*)d_in[11];
    const float* Wm2      = (const float*)d_in[12];
    const float* bm2      = (const float*)d_in[13];
    const float* Wm1      = (const float*)d_in[14];
    const float* bm1      = (const float*)d_in[15];
    const float* W_ru     = (const float*)d_in[16];
    const float* b_ru     = (const float*)d_in[17];
    const float* W_cand   = (const float*)d_in[18];
    const float* b_cand   = (const float*)d_in[19];
    const float* Wp1      = (const float*)d_in[20];
    const float* bp1      = (const float*)d_in[21];
    const float* Wp2      = (const float*)d_in[22];
    const float* bp2      = (const float*)d_in[23];

    float* out      = (float*)d_out;
    float* out_pred = out;                 // (B,N,1) = 1600 floats
    float* out_dy   = out + BN*NN;         // (T,B,N,N)

    const int SMEM_BYTES = SMEMF * 4;      // 110848
    cudaFuncSetAttribute(mega_kernel, cudaFuncAttributeMaxDynamicSharedMemorySize, SMEM_BYTES);

    mega_kernel<<<GRID, NTH, SMEM_BYTES>>>(x, nf, W_s2d, b_s2d, W_rz, b_rz, W_h, b_h,
                                           Wc2, bc2, Wc1, bc1, Wm2, bm2, Wm1, bm1,
                                           W_ru, b_ru, W_cand, b_cand,
                                           Wp1, bp1, Wp2, bp2, out_pred, out_dy);
}

// round 13
// speedup vs baseline: 1.9337x; 1.2788x over previous
#include <cuda_runtime.h>
#include <math.h>

#define BN   8
#define TT   12
#define NN   200
#define CIN  2
#define HH   64
#define DD   32
#define HST  64
#define GW   66      // CIN + HH
#define GIN  198     // GW * 3
#define GROUPS 8
#define GPB    36
#define GRID   (GROUPS*GPB)   // 288 blocks, 2 per SM, all co-resident
#define NTH    512
#define MAXR   6

// ---- smem layout (floats), per CTA ----
#define OFF_A    0          // A tile: 6*200 = 1200
#define OFF_P    1200       // Pg 6*32 | Pm 6*32 = 384
#define OFF_SD   1584       // state_dy 6*32 = 192
#define OFF_U    1776       // u 6*64 = 384
#define OFF_W    2160       // wc1 32 | wm1 32
#define OFF_GRU  2224       // 6 warps * 96 = 576
#define OFF_Z    2800       // Z 6*198 = 1188 (pad to 1200)
#define OFF_CP   4000       // max(QS 14400, spmm 5940, gemm 6144)
#define SMEMF    18400      // *4 = 73600 bytes
#define QS_G     OFF_CP                  // 200*36
#define QS_M     (OFF_CP + 7200)         // 200*36

// ---------------- device scratch ----------------
__device__ float g_Qg[BN*NN*DD];
__device__ float g_Qm[BN*NN*DD];
__device__ float g_X1[BN*NN*GW];
__device__ float g_X0r[BN*NN*GW];   // [xt | state]
__device__ float g_X0c[BN*NN*GW];   // [xt | rr*state]
__device__ unsigned g_cnt[GROUPS];
__device__ unsigned g_gen[GROUPS];

__device__ __forceinline__ float fsig(float v){
    return __fdividef(1.f, 1.f + __expf(-v));
}

// group-local barrier among the GPB co-resident blocks of one group
__device__ __forceinline__ void group_barrier(int grp){
    __syncthreads();
    if (threadIdx.x == 0){
        volatile unsigned* vg = &g_gen[grp];
        unsigned gen = *vg;
        __threadfence();
        if (atomicAdd(&g_cnt[grp], 1u) == GPB - 1u){
            g_cnt[grp] = 0u;
            __threadfence();
            *vg = gen + 1u;
        } else {
            while (*vg == gen) { }
        }
        __threadfence();
    }
    __syncthreads();
}

// ---- gru for own rows (warp per local row) ----
__device__ __forceinline__ void gru_step(float* sb, int b, int row0, int nrows, int t,
    const float* __restrict__ x,
    const float* __restrict__ W_rz, const float* __restrict__ b_rz,
    const float* __restrict__ W_h,  const float* __restrict__ b_h,
    const float* __restrict__ Wc2,  const float* __restrict__ bc2,
    const float* __restrict__ Wm2,  const float* __restrict__ bm2)
{
    int warp = threadIdx.x >> 5, lane = threadIdx.x & 31;
    if (warp < nrows){
        int n  = row0 + warp;
        int gi = b*NN + n;
        float* sdp = sb + OFF_SD  + warp*32;
        float* sc  = sb + OFF_GRU + warp*96;   // rs[32] | sv[32]
        const float* xr = x + ((b*TT + t)*NN + n)*CIN;
        if (lane < CIN){
            float xv = xr[lane];
            g_X0r[gi*GW + lane] = xv;
            g_X0c[gi*GW + lane] = xv;
        }
        float inp1 = __ldg(&xr[0]);
        float sdv  = sdp[lane];
        float accr = b_rz[lane]      + inp1 * W_rz[lane];
        float accz = b_rz[lane + 32] + inp1 * W_rz[lane + 32];
        #pragma unroll
        for (int d = 0; d < 32; d++){
            float v = sdp[d];
            accr = fmaf(v, W_rz[(1 + d)*64 + lane],      accr);
            accz = fmaf(v, W_rz[(1 + d)*64 + lane + 32], accz);
        }
        float r = fsig(accr), z = fsig(accz);
        sc[lane] = r * sdv;
        __syncwarp();
        float acch = b_h[lane] + inp1 * W_h[lane];
        #pragma unroll
        for (int d = 0; d < 32; d++) acch = fmaf(sc[d], W_h[(1 + d)*32 + lane], acch);
        float h  = tanhf(acch);
        float nd = z * sdv + (1.f - z) * h;
        sdp[lane] = nd;
        float s = fmaxf(nd, 0.f);
        sc[32 + lane] = s;
        __syncwarp();
        float pg = 0.f, qg = bc2[lane], pm = 0.f, qm = bm2[lane];
        #pragma unroll
        for (int d = 0; d < 32; d++){
            float v = sc[32 + d];
            pg = fmaf(v, Wc2[d*32 + lane],        pg);
            qg = fmaf(v, Wc2[(32 + d)*32 + lane], qg);
            pm = fmaf(v, Wm2[d*32 + lane],        pm);
            qm = fmaf(v, Wm2[(32 + d)*32 + lane], qm);
        }
        sb[OFF_P +       warp*32 + lane] = pg;
        sb[OFF_P + 192 + warp*32 + lane] = pm;
        g_Qg[gi*DD + lane] = qg;
        g_Qm[gi*DD + lane] = qm;
    }
}

// ---- split-K core: own rows of A_smem @ M(200xGW, global) -> Cp smem ----
// 15 j-groups (10x14 + 5x12 columns) x 33 col-pairs = 495 threads
__device__ __forceinline__ void spmm_partials(float* sb, const float* __restrict__ M,
                                              int b, int tid)
{
    if (tid < 495){
        int jg = tid/33, c2 = tid - jg*33;
        int j0   = (jg < 10) ? jg*14 : 140 + (jg - 10)*12;
        int jlen = (jg < 10) ? 14 : 12;
        const float* Mb = M + b*NN*GW + 2*c2;
        float2 acc[MAXR];
        #pragma unroll
        for (int il = 0; il < MAXR; il++){ acc[il].x = 0.f; acc[il].y = 0.f; }
        #pragma unroll 2
        for (int j = j0; j < j0 + jlen; j += 2){
            float2 x0 = __ldg((const float2*)&Mb[j*GW]);
            float2 x1 = __ldg((const float2*)&Mb[(j+1)*GW]);
            #pragma unroll
            for (int il = 0; il < MAXR; il++){
                float2 a = *(const float2*)&sb[OFF_A + il*200 + j];
                acc[il].x = fmaf(a.x, x0.x, acc[il].x);
                acc[il].y = fmaf(a.x, x0.y, acc[il].y);
                acc[il].x = fmaf(a.y, x1.x, acc[il].x);
                acc[il].y = fmaf(a.y, x1.y, acc[il].y);
            }
        }
        #pragma unroll
        for (int il = 0; il < MAXR; il++)
            *(float2*)&sb[OFF_CP + (jg*MAXR + il)*66 + 2*c2] = acc[il];
    }
}

// ---- hop: X1 rows = A_smem @ X0 ----
__device__ __forceinline__ void hop_phase(float* sb, int b, int row0, int nrows, int tid,
                                          const float* __restrict__ X0)
{
    spmm_partials(sb, X0, b, tid);
    __syncthreads();
    for (int e = tid; e < nrows*GW; e += NTH){
        int il = e/GW, c = e - il*GW;
        float s = 0.f;
        #pragma unroll
        for (int g = 0; g < 15; g++) s += sb[OFF_CP + (g*MAXR + il)*66 + c];
        g_X1[(b*NN + row0 + il)*GW + c] = s;
    }
}

// ---- conv: X2 = A_smem@X1 ; Z=[X0|X1|X2] @ W (il-blocked split-K GEMM) ------
template<int FOUT, int CAND>
__device__ __forceinline__ void conv_phase(float* sb, int b, int row0, int nrows, int tid,
                                           const float* __restrict__ W,
                                           const float* __restrict__ bias)
{
    const float* __restrict__ X0 = CAND ? g_X0c : g_X0r;
    spmm_partials(sb, g_X1, b, tid);
    __syncthreads();
    for (int e = tid; e < nrows*GW; e += NTH){
        int il = e/GW, c = e - il*GW;
        float s = 0.f;
        #pragma unroll
        for (int g = 0; g < 15; g++) s += sb[OFF_CP + (g*MAXR + il)*66 + c];
        int row = (b*NN + row0 + il)*GW + c;
        sb[OFF_Z + il*GIN + 2*GW + c] = s;            // X2
        sb[OFF_Z + il*GIN +   GW + c] = g_X1[row];    // X1
        sb[OFF_Z + il*GIN +        c] = X0[row];      // X0
    }
    __syncthreads();
    // il-blocked split-K GEMM: thread = f-quad x il-group(2x3 rows) x k-chunk
    constexpr int NF4 = FOUT/4;            // 32 or 16
    constexpr int KG  = (FOUT == 128) ? 8 : 16;
    {
        int f4  = tid % NF4;
        int ilg = (tid / NF4) & 1;
        int kg  = tid / (NF4*2);
        int il0 = ilg*3;
        int kc0, klen;
        if (FOUT == 128){ kc0 = (kg < 6) ? kg*25 : 150 + (kg - 6)*24; klen = (kg < 6) ? 25 : 24; }
        else            { kc0 = (kg < 6) ? kg*13 : 78  + (kg - 6)*12; klen = (kg < 6) ? 13 : 12; }
        const float4* Wv = (const float4*)W;
        float4 acc0, acc1, acc2;
        acc0.x=0.f;acc0.y=0.f;acc0.z=0.f;acc0.w=0.f;
        acc1 = acc0; acc2 = acc0;
        const float* z0 = sb + OFF_Z + (il0+0)*GIN;
        const float* z1 = sb + OFF_Z + (il0+1)*GIN;
        const float* z2 = sb + OFF_Z + (il0+2)*GIN;
        #pragma unroll 2
        for (int k = kc0; k < kc0 + klen; k++){
            float4 w = __ldg(&Wv[k*NF4 + f4]);
            float a0 = z0[k], a1 = z1[k], a2 = z2[k];
            acc0.x = fmaf(a0, w.x, acc0.x); acc0.y = fmaf(a0, w.y, acc0.y);
            acc0.z = fmaf(a0, w.z, acc0.z); acc0.w = fmaf(a0, w.w, acc0.w);
            acc1.x = fmaf(a1, w.x, acc1.x); acc1.y = fmaf(a1, w.y, acc1.y);
            acc1.z = fmaf(a1, w.z, acc1.z); acc1.w = fmaf(a1, w.w, acc1.w);
            acc2.x = fmaf(a2, w.x, acc2.x); acc2.y = fmaf(a2, w.y, acc2.y);
            acc2.z = fmaf(a2, w.z, acc2.z); acc2.w = fmaf(a2, w.w, acc2.w);
        }
        *(float4*)&sb[OFF_CP + (kg*MAXR + il0+0)*FOUT + 4*f4] = acc0;
        *(float4*)&sb[OFF_CP + (kg*MAXR + il0+1)*FOUT + 4*f4] = acc1;
        *(float4*)&sb[OFF_CP + (kg*MAXR + il0+2)*FOUT + 4*f4] = acc2;
    }
    __syncthreads();
    // reduce partials + bias + activation + epilogue
    for (int e = tid; e < MAXR*FOUT; e += NTH){
        int il = e / FOUT, f = e - il*FOUT;
        float s = __ldg(&bias[f]);
        #pragma unroll
        for (int g = 0; g < KG; g++) s += sb[OFF_CP + (g*MAXR + il)*FOUT + f];
        if (il < nrows){
            int gi = b*NN + row0 + il;
            if (!CAND){
                float rv = fsig(s);
                if (f < HH) g_X0c[gi*GW + CIN + f] = rv * g_X0r[gi*GW + CIN + f];
                else        sb[OFF_U + il*HH + (f - HH)] = rv;
            } else {
                float cv = tanhf(s);
                float u  = sb[OFF_U + il*HH + f];
                float so = g_X0r[gi*GW + CIN + f];
                g_X0r[gi*GW + CIN + f] = u*so + (1.f - u)*cv;
            }
        }
    }
}

// ============================ megakernel =====================================
__global__ void __launch_bounds__(NTH, 2) mega_kernel(
    const float* __restrict__ x,     const float* __restrict__ nf,
    const float* __restrict__ W_s2d, const float* __restrict__ b_s2d,
    const float* __restrict__ W_rz,  const float* __restrict__ b_rz,
    const float* __restrict__ W_h,   const float* __restrict__ b_h,
    const float* __restrict__ Wc2,   const float* __restrict__ bc2,
    const float* __restrict__ Wc1,   const float* __restrict__ bc1,
    const float* __restrict__ Wm2,   const float* __restrict__ bm2,
    const float* __restrict__ Wm1,   const float* __restrict__ bm1,
    const float* __restrict__ W_ru,  const float* __restrict__ b_ru,
    const float* __restrict__ W_cand,const float* __restrict__ b_cand,
    const float* __restrict__ Wp1,   const float* __restrict__ bp1,
    const float* __restrict__ Wp2,   const float* __restrict__ bp2,
    float* __restrict__ out_pred,    float* __restrict__ out_dy)
{
    extern __shared__ float sb[];
    int bid = blockIdx.x, tid = threadIdx.x;
    int grp = bid / GPB, rk = bid - grp*GPB;
    int b = grp;
    int warp = tid >> 5, lane = tid & 31;
    // 36 blocks: first 20 own 6 rows, last 16 own 5 rows
    int row0  = (rk < 20) ? rk*6 : 120 + (rk - 20)*5;
    int nrows = (rk < 20) ? 6 : 5;

    // ---------------- init ----------------
    for (int e = tid; e < nrows*DD; e += NTH){
        int l = e/DD, d = e - l*DD;
        int n = row0 + l;
        float acc = b_s2d[d];
        #pragma unroll 8
        for (int k = 0; k < HST; k++) acc = fmaf(nf[n*HST + k], W_s2d[k*DD + d], acc);
        sb[OFF_SD + l*DD + d] = acc;
    }
    for (int e = tid; e < nrows*HH; e += NTH){
        int l = e/HH, f = e - l*HH;
        g_X0r[(b*NN + row0 + l)*GW + CIN + f] = 0.f;
    }
    if (tid < 32) sb[OFF_W + tid] = Wc1[tid];
    else if (tid < 64) sb[OFF_W + tid] = Wm1[tid - 32];
    __syncthreads();
    gru_step(sb, b, row0, nrows, 0, x, W_rz, b_rz, W_h, b_h, Wc2, bc2, Wm2, bm2);
    group_barrier(grp);

    float bc1v = __ldg(&bc1[0]), bm1v = __ldg(&bm1[0]);

    for (int t = 0; t < TT; t++){
        // -------- phase 1: pair (A rows -> smem + out_dy) then hop_r --------
        {
            // stage Q into smem at stride 36 (16B-aligned float4, conflict-free)
            for (int e = tid; e < NN*DD; e += NTH){
                int j = e >> 5, d = e & 31;
                sb[QS_G + j*36 + d] = g_Qg[b*NN*DD + e];
                sb[QS_M + j*36 + d] = g_Qm[b*NN*DD + e];
            }
            __syncthreads();
            if (tid < 400){
                int j  = tid % 200;
                int ig = tid / 200;         // 0..1, each 3 local rows
                float ga[3] = {bc1v, bc1v, bc1v};
                float ma[3] = {bm1v, bm1v, bm1v};
                #pragma unroll
                for (int dc = 0; dc < 32; dc += 4){
                    float4 qg = *(const float4*)&sb[QS_G + j*36 + dc];
                    float4 qm = *(const float4*)&sb[QS_M + j*36 + dc];
                    float4 wg = *(const float4*)&sb[OFF_W + dc];
                    float4 wm = *(const float4*)&sb[OFF_W + 32 + dc];
                    #pragma unroll
                    for (int q = 0; q < 3; q++){
                        int l = ig*3 + q;
                        float4 pg = *(const float4*)&sb[OFF_P +       l*32 + dc];
                        float4 pm = *(const float4*)&sb[OFF_P + 192 + l*32 + dc];
                        ga[q] = fmaf(fmaxf(pg.x + qg.x, 0.f), wg.x, ga[q]);
                        ga[q] = fmaf(fmaxf(pg.y + qg.y, 0.f), wg.y, ga[q]);
                        ga[q] = fmaf(fmaxf(pg.z + qg.z, 0.f), wg.z, ga[q]);
                        ga[q] = fmaf(fmaxf(pg.w + qg.w, 0.f), wg.w, ga[q]);
                        ma[q] = fmaf(fmaxf(pm.x + qm.x, 0.f), wm.x, ma[q]);
                        ma[q] = fmaf(fmaxf(pm.y + qm.y, 0.f), wm.y, ma[q]);
                        ma[q] = fmaf(fmaxf(pm.z + qm.z, 0.f), wm.z, ma[q]);
                        ma[q] = fmaf(fmaxf(pm.w + qm.w, 0.f), wm.w, ma[q]);
                    }
                }
                #pragma unroll
                for (int q = 0; q < 3; q++){
                    int l = ig*3 + q;
                    if (l < nrows){
                        float A = ga[q] * fsig(ma[q]);
                        sb[OFF_A + l*200 + j] = A;
                        out_dy[(((size_t)t*BN + b)*NN + row0 + l)*NN + j] = A;
                    }
                }
            }
            __syncthreads();
            hop_phase(sb, b, row0, nrows, tid, g_X0r);
        }
        group_barrier(grp);

        conv_phase<128, 0>(sb, b, row0, nrows, tid, W_ru, b_ru);
        group_barrier(grp);

        hop_phase(sb, b, row0, nrows, tid, g_X0c);
        group_barrier(grp);

        conv_phase<64, 1>(sb, b, row0, nrows, tid, W_cand, b_cand);
        if (t < TT-1){
            __syncthreads();
            gru_step(sb, b, row0, nrows, t+1, x, W_rz, b_rz, W_h, b_h, Wc2, bc2, Wm2, bm2);
        }
        group_barrier(grp);
    }

    // ---------------- prediction head (own rows; no barrier needed) -------------
    if (warp < nrows){
        int gi = b*NN + row0 + warp;
        float s0 = g_X0r[gi*GW + CIN + lane];
        float s1 = g_X0r[gi*GW + CIN + 32 + lane];
        float a0 = bp1[lane], a1 = bp1[lane + 32];
        #pragma unroll
        for (int k = 0; k < 32; k++){
            float sk = __shfl_sync(0xffffffffu, s0, k);
            a0 = fmaf(sk, Wp1[k*HH + lane],      a0);
            a1 = fmaf(sk, Wp1[k*HH + lane + 32], a1);
        }
        #pragma unroll
        for (int k = 0; k < 32; k++){
            float sk = __shfl_sync(0xffffffffu, s1, k);
            a0 = fmaf(sk, Wp1[(32 + k)*HH + lane],      a0);
            a1 = fmaf(sk, Wp1[(32 + k)*HH + lane + 32], a1);
        }
        float h0 = a0 > 0.f ? a0 : 0.01f*a0;
        float h1 = a1 > 0.f ? a1 : 0.01f*a1;
        float r = h0*Wp2[lane] + h1*Wp2[lane + 32];
        #pragma unroll
        for (int off = 16; off > 0; off >>= 1) r += __shfl_down_sync(0xffffffffu, r, off);
        if (lane == 0) out_pred[gi] = r + bp2[0];
    }
}

// ---------------- launch ------------------------------------------------------
extern "C" void kernel_launch(void* const* d_in, const int* in_sizes, int n_in,
                              void* d_out, int out_size)
{
    (void)in_sizes; (void)n_in; (void)out_size;
    const float* x        = (const float*)d_in[0];
    const float* nf       = (const float*)d_in[1];
    const float* W_s2d    = (const float*)d_in[2];
    const float* b_s2d    = (const float*)d_in[3];
    const float* W_rz     = (const float*)d_in[4];
    const float* b_rz     = (const float*)d_in[5];
    const float* W_h      = (const float*)d_in[6];
    const float* b_h      = (const float*)d_in[7];
    const float* Wc2      = (const float*)d_in[8];
    const float* bc2      = (const float*)d_in[9];
    const float* Wc1      = (const float*)d_in[10];
    const float* bc1      = (const float*)d_in[11];
    const float* Wm2      = (const float*)d_in[12];
    const float* bm2      = (const float*)d_in[13];
    const float* Wm1      = (const float*)d_in[14];
    const float* bm1      = (const float*)d_in[15];
    const float* W_ru     = (const float*)d_in[16];
    const float* b_ru     = (const float*)d_in[17];
    const float* W_cand   = (const float*)d_in[18];
    const float* b_cand   = (const float*)d_in[19];
    const float* Wp1      = (const float*)d_in[20];
    const float* bp1      = (const float*)d_in[21];
    const float* Wp2      = (const float*)d_in[22];
    const float* bp2      = (const float*)d_in[23];

    float* out      = (float*)d_out;
    float* out_pred = out;                 // (B,N,1) = 1600 floats
    float* out_dy   = out + BN*NN;         // (T,B,N,N)

    const int SMEM_BYTES = SMEMF * 4;      // 73600
    cudaFuncSetAttribute(mega_kernel, cudaFuncAttributeMaxDynamicSharedMemorySize, SMEM_BYTES);

    mega_kernel<<<GRID, NTH, SMEM_BYTES>>>(x, nf, W_s2d, b_s2d, W_rz, b_rz, W_h, b_h,
                                           Wc2, bc2, Wc1, bc1, Wm2, bm2, Wm1, bm1,
                                           W_ru, b_ru, W_cand, b_cand,
                                           Wp1, bp1, Wp2, bp2, out_pred, out_dy);
}